// round 10
// baseline (speedup 1.0000x reference)
#include <cuda_runtime.h>
#include <cuda_bf16.h>

// LinearSpline activation, division-free, channel-folded:
//   t  = x * (s[c]*6.25f)                 (6.25f == float(1/0.16), exact)
//   tc = clamp(t, -25.0f, 24.0f)          (== reference clip-then-divide)
//   ip = (int)floor(tc);  fr = t - ip     (fr from unclamped t, per reference)
//   out = fma(fr, C1-C0, C0)   where (C0,C1) = (c[z+ip]/s, c[z+ip+1]/s)
//
// R10 = R9 + software pipelining: the next trip's two LDG.128 are issued
// BEFORE the current trip's dependent compute/store, so the warp always has
// loads in flight across the LDS-chain + STG phase (closes the scoreboard
// dead-time that capped DRAM at ~66% with every pipe under 45%).
// Config frozen at the R9 winner: 2 CTAs x 768 thr (48 warps), 13.3KB table
// (L1 ~200KB), lean folded chain, no cache hints.

#define NUM_ACT 64
#define SIZE    51
#define TABLE   (NUM_ACT * SIZE)   // 3264

__global__ __launch_bounds__(768, 2)
void linear_spline_kernel(const float4* __restrict__ x,
                          const float*  __restrict__ coef,
                          const float*  __restrict__ scale,
                          float4*       __restrict__ out,
                          int n4)
{
    __shared__ float sc[TABLE];         // c[i]/s[c], 13.3 KB
    __shared__ float s625[NUM_ACT];     // s[c] * 6.25f

    for (int i = threadIdx.x; i < TABLE; i += 768) {
        int   c  = i / SIZE;
        float rs = 1.0f / scale[c];                      // exact for s==1
        sc[i] = coef[i] * rs;
    }
    if (threadIdx.x < NUM_ACT) {
        s625[threadIdx.x] = scale[threadIdx.x] * 6.25f;  // exact for s==1
    }
    __syncthreads();

    const int stride = gridDim.x * blockDim.x;
    int i = blockIdx.x * blockDim.x + threadIdx.x;

    // ~10 warp-ops + 2 LDS.32 per element. Max idx = 63*51+49+1 = 3263.
    #define ELEM(v, ov, zk_, sg_) {                      \
        float t  = (v) * (sg_);                          \
        float tc = fminf(fmaxf(t, -25.0f), 24.0f);       \
        int   ip = __float2int_rd(tc);                   \
        float fr = t - (float)ip;                        \
        int p = (zk_) + ip;                              \
        float c0 = sc[p];                                \
        float c1 = sc[p + 1];                            \
        (ov) = fmaf(fr, c1 - c0, c0); }

    #define PAIR(ii, xa_, xb_) {                                  \
        const int jj = (ii) + stride;                             \
        const int ca = ((ii) >> 12) & (NUM_ACT - 1);              \
        const int cb = (jj  >> 12) & (NUM_ACT - 1);               \
        const float sga = s625[ca];                               \
        const float sgb = s625[cb];                               \
        const int zka = ca * SIZE + SIZE / 2;                     \
        const int zkb = cb * SIZE + SIZE / 2;                     \
        float4 oa, ob;                                            \
        ELEM((xa_).x, oa.x, zka, sga)                             \
        ELEM((xa_).y, oa.y, zka, sga)                             \
        ELEM((xa_).z, oa.z, zka, sga)                             \
        ELEM((xa_).w, oa.w, zka, sga)                             \
        ELEM((xb_).x, ob.x, zkb, sgb)                             \
        ELEM((xb_).y, ob.y, zkb, sgb)                             \
        ELEM((xb_).z, ob.z, zkb, sgb)                             \
        ELEM((xb_).w, ob.w, zkb, sgb)                             \
        out[(ii)] = oa;                                           \
        out[jj]   = ob; }

    if (i + stride < n4) {
        // Prologue: first pair in flight.
        float4 xa = x[i];
        float4 xb = x[i + stride];

        // Steady state: prefetch pair k+1, then compute/store pair k.
        for (; i + 3 * stride < n4; i += 2 * stride) {
            float4 na = x[i + 2 * stride];
            float4 nb = x[i + 3 * stride];
            PAIR(i, xa, xb)
            xa = na;
            xb = nb;
        }
        // Epilogue: last prefetched pair.
        PAIR(i, xa, xb)
        i += 2 * stride;
    }
    // Tail: at most one remaining element.
    if (i < n4) {
        float4 xv = x[i];
        const int c = (i >> 12) & (NUM_ACT - 1);
        const float sg = s625[c];
        const int zk = c * SIZE + SIZE / 2;
        float4 o;
        ELEM(xv.x, o.x, zk, sg)
        ELEM(xv.y, o.y, zk, sg)
        ELEM(xv.z, o.z, zk, sg)
        ELEM(xv.w, o.w, zk, sg)
        out[i] = o;
    }
    #undef PAIR
    #undef ELEM
}

extern "C" void kernel_launch(void* const* d_in, const int* in_sizes, int n_in,
                              void* d_out, int out_size)
{
    const float* x     = (const float*)d_in[0];
    const float* coef  = (const float*)d_in[1];
    const float* scale = (const float*)d_in[2];
    float* out         = (float*)d_out;

    const int n  = in_sizes[0];   // 33,554,432
    const int n4 = n / 4;         // 8,388,608

    const int threads = 768;
    const int blocks  = 148 * 2;  // 2 CTAs/SM = 48 warps, smem ~13KB, L1 ~200KB

    linear_spline_kernel<<<blocks, threads>>>(
        (const float4*)x, coef, scale, (float4*)out, n4);
}